// round 12
// baseline (speedup 1.0000x reference)
#include <cuda_runtime.h>
#include <cstdint>
#include <math.h>

// ---------------------------------------------------------------------------
// Hybrid router. B*S=16384 tokens, IN=2048, E=16, D=128, A=128, R=4, top_k=2.
// TWO launches of the SAME kernel (same smem config):
//   mode=0, grid=16 : parallel prep, block f computes k[f]/Mk[f]/tables[:,f];
//                     block 0 also computes rank-4 moments -> __device__ globals
//   mode=1, grid=148: load tables global->smem, stream tokens.
// Main loop: TPB=448, 14 warps = 7 pairs, pair processes 4 tokens, sub=0 rows
// 0..9 / sub=1 rows 10..19, plain fp32 FMA, hidden via direct LDG with
// 4-buffer lookahead-2 rotation (covers 577-cyc DRAM latency).
// ---------------------------------------------------------------------------

#define NTOK 16384
#define GRID 148
#define TPB  448
#define NWARP 14
#define NPAIR 7
#define PREP_GRID 16

#define TSTRIDE 35
#define TSIZE   544

// smem layout (floats)
#define SW_F      40960            // 20 rows x 2048 weights (16 Wv + 4 w1)
#define STAB_F    (7 * TSIZE)      // 3808
#define SMISC_F   64
#define SFIN_F    (NPAIR * 84)     // per-pair final sums: 4 tok x 21
#define SPART_F   (NWARP * 736)    // per-warp reduce scratch (also prep scratch)
#define OFF_STAB  SW_F
#define OFF_SMISC (OFF_STAB + STAB_F)
#define OFF_SFIN  (OFF_SMISC + SMISC_F)
#define OFF_SPART (OFF_SFIN + SFIN_F)
#define SMEM_FLOATS (OFF_SPART + SPART_F)
#define SMEM_BYTES  (SMEM_FLOATS * 4)

__device__ float g_tab[7 * TSIZE];
__device__ float g_misc[SMISC_F];

// ---------------------------------------------------------------------------
__device__ __forceinline__ float wred(float v) {
    #pragma unroll
    for (int m = 16; m; m >>= 1) v += __shfl_xor_sync(~0u, v, m);
    return v;
}
__device__ __forceinline__ void pair_bar(int pair) {
    asm volatile("bar.sync %0, 64;" :: "r"(pair + 1) : "memory");
}

// one j-slice of the 10x4 FMA block
__device__ __forceinline__ void slice_fma(float acc[10][4], const float4 hv[4],
                                          const float* swr, int j, int lane) {
    const float4* wj = (const float4*)(swr + j * 128) + lane;
    #pragma unroll
    for (int r = 0; r < 10; r++) {
        float4 wv = wj[r * 512];
        #pragma unroll
        for (int i = 0; i < 4; i++) {
            acc[r][i] = fmaf(hv[i].x, wv.x, acc[r][i]);
            acc[r][i] = fmaf(hv[i].y, wv.y, acc[r][i]);
            acc[r][i] = fmaf(hv[i].z, wv.z, acc[r][i]);
            acc[r][i] = fmaf(hv[i].w, wv.w, acc[r][i]);
        }
    }
}

// ---------------------------------------------------------------------------
__global__ void __launch_bounds__(TPB, 1)
fused_kernel(const float* __restrict__ hidden, const float* __restrict__ ee,
             const float* __restrict__ gamma, const float* __restrict__ beta,
             const float* __restrict__ wv_w, const float* __restrict__ wv_b,
             const float* __restrict__ w1, const float* __restrict__ b1,
             const float* __restrict__ w2, const float* __restrict__ b2,
             const float* __restrict__ wq, const float* __restrict__ wk,
             float* __restrict__ out, int mode)
{
    extern __shared__ float smem[];
    float* sw    = smem;
    float* stab  = smem + OFF_STAB;
    float* smisc = smem + OFF_SMISC;
    float* sfin  = smem + OFF_SFIN;
    float* spart = smem + OFF_SPART;

    int tid = threadIdx.x, lane = tid & 31, warp = tid >> 5;
    int pair = warp >> 1, sub = warp & 1;

    if (mode == 0) {
        // ============ prep launch (grid=16, block f handles row f) ============
        int f = blockIdx.x;
        float* sge  = spart;           // 2048: LN(ee), later reused for final Mk
        float* skv  = spart + 2048;    // 128:  k[f][:]
        float* smkp = spart + 4096;    // NWARP*128: Mk partials
        float* sred = sfin;            // scratch

        // --- LN of expert_embedding over all 2048 (redundant per block) ---
        {
            float ls = 0.f, lq = 0.f;
            for (int i = tid; i < 2048; i += TPB) {
                float v = ee[i];
                sge[i] = v; ls += v; lq += v * v;
            }
            ls = wred(ls); lq = wred(lq);
            if (lane == 0) { sred[warp] = ls; sred[16 + warp] = lq; }
            __syncthreads();
            if (tid == 0) {
                float s = 0.f, q = 0.f;
                for (int i = 0; i < NWARP; i++) { s += sred[i]; q += sred[16 + i]; }
                float mu = s * (1.0f / 2048.0f);
                float var = q * (1.0f / 2048.0f) - mu * mu;
                sred[32] = mu; sred[33] = rsqrtf(var + 1e-5f);
            }
            __syncthreads();
            float mu = sred[32], rs = sred[33];
            for (int i = tid; i < 2048; i += TPB)
                sge[i] = (sge[i] - mu) * rs * gamma[i] + beta[i];
            __syncthreads();
        }

        // --- k[f][a]: warp handles 8-chunks strided by NWARP*8 ---
        {
            float4 g4 = ((const float4*)(sge + f * 128))[lane];
            for (int a0 = warp * 8; a0 < 128; a0 += NWARP * 8) {
                float p[8];
                #pragma unroll
                for (int q = 0; q < 8; q++) {
                    float4 w4 = ((const float4*)(wk + (a0 + q) * 128))[lane];
                    p[q] = fmaf(g4.x, w4.x, fmaf(g4.y, w4.y,
                           fmaf(g4.z, w4.z, g4.w * w4.w)));
                }
                #pragma unroll
                for (int m = 16; m; m >>= 1) {
                    #pragma unroll
                    for (int q = 0; q < 8; q++)
                        p[q] += __shfl_xor_sync(~0u, p[q], m);
                }
                if (lane == 0) {
                    #pragma unroll
                    for (int q = 0; q < 8; q++) skv[a0 + q] = p[q];
                }
            }
        }
        __syncthreads();

        // --- Mk[f][d] partials over strided a-chunks, lanes cover d ---
        {
            const float4* wq4 = (const float4*)wq + lane;
            float4 a4 = make_float4(0.f, 0.f, 0.f, 0.f);
            for (int a0 = warp * 8; a0 < 128; a0 += NWARP * 8) {
                #pragma unroll
                for (int aa = 0; aa < 8; aa++) {
                    int a = a0 + aa;
                    float s = skv[a];
                    float4 w4 = wq4[a * 32];
                    a4.x = fmaf(s, w4.x, a4.x);
                    a4.y = fmaf(s, w4.y, a4.y);
                    a4.z = fmaf(s, w4.z, a4.z);
                    a4.w = fmaf(s, w4.w, a4.w);
                }
            }
            ((float4*)(smkp + warp * 128))[lane] = a4;
        }
        __syncthreads();
        // reduce NWARP partials -> final Mk row (reuse sge[0..127])
        if (tid < 128) {
            float s = 0.f;
            #pragma unroll
            for (int w = 0; w < NWARP; w++) s += smkp[w * 128 + tid];
            sge[tid] = s * 0.08838834764831845f;  // 1/sqrt(128)
        }
        __syncthreads();

        // --- tables T0..T3, Tb, Gs, Bs for (e, f), e strided by NWARP ---
        for (int e = warp; e < 16; e += NWARP) {
            int o = e * 128 + lane * 4;
            float4 mk = ((const float4*)sge)[lane];
            float4 ga = *(const float4*)(gamma + o);
            float4 be = *(const float4*)(beta + o);
            float4 bb = *(const float4*)(b2 + o);
            float4 wA = *(const float4*)(w2 + (o + 0) * 4);
            float4 wB = *(const float4*)(w2 + (o + 1) * 4);
            float4 wC = *(const float4*)(w2 + (o + 2) * 4);
            float4 wD = *(const float4*)(w2 + (o + 3) * 4);
            float m0 = mk.x * ga.x, m1 = mk.y * ga.y, m2 = mk.z * ga.z, m3 = mk.w * ga.w;
            float t0 = m0 * wA.x + m1 * wB.x + m2 * wC.x + m3 * wD.x;
            float t1 = m0 * wA.y + m1 * wB.y + m2 * wC.y + m3 * wD.y;
            float t2 = m0 * wA.z + m1 * wB.z + m2 * wC.z + m3 * wD.z;
            float t3 = m0 * wA.w + m1 * wB.w + m2 * wC.w + m3 * wD.w;
            float tb = m0 * bb.x + m1 * bb.y + m2 * bb.z + m3 * bb.w;
            float gs = m0 + m1 + m2 + m3;
            float bs = mk.x * be.x + mk.y * be.y + mk.z * be.z + mk.w * be.w;
            #pragma unroll
            for (int m = 16; m; m >>= 1) {
                t0 += __shfl_xor_sync(~0u, t0, m);
                t1 += __shfl_xor_sync(~0u, t1, m);
                t2 += __shfl_xor_sync(~0u, t2, m);
                t3 += __shfl_xor_sync(~0u, t3, m);
                tb += __shfl_xor_sync(~0u, tb, m);
                gs += __shfl_xor_sync(~0u, gs, m);
                bs += __shfl_xor_sync(~0u, bs, m);
            }
            if (lane == 0) {
                int oo = e * TSTRIDE + f;
                g_tab[0 * TSIZE + oo] = t0;
                g_tab[1 * TSIZE + oo] = t1;
                g_tab[2 * TSIZE + oo] = t2;
                g_tab[3 * TSIZE + oo] = t3;
                g_tab[4 * TSIZE + oo] = tb;
                g_tab[5 * TSIZE + oo] = gs;
                g_tab[6 * TSIZE + oo] = bs;
            }
        }

        // --- rank-4 moments (block 0 only) ---
        if (blockIdx.x == 0) {
            float p[26];
            #pragma unroll
            for (int q = 0; q < 26; q++) p[q] = 0.f;
            for (int o = tid; o < 2048; o += TPB) {
                float4 w4 = *(const float4*)(w2 + o * 4);
                float b = b2[o];
                float w0v = w4.x, w1v = w4.y, w2v = w4.z, w3v = w4.w;
                p[0] += w0v; p[1] += w1v; p[2] += w2v; p[3] += w3v;
                p[4]  += w0v * w0v; p[5]  += w0v * w1v; p[6]  += w0v * w2v; p[7]  += w0v * w3v;
                p[8]  += w1v * w0v; p[9]  += w1v * w1v; p[10] += w1v * w2v; p[11] += w1v * w3v;
                p[12] += w2v * w0v; p[13] += w2v * w1v; p[14] += w2v * w2v; p[15] += w2v * w3v;
                p[16] += w3v * w0v; p[17] += w3v * w1v; p[18] += w3v * w2v; p[19] += w3v * w3v;
                p[20] += w0v * b; p[21] += w1v * b; p[22] += w2v * b; p[23] += w3v * b;
                p[24] += b; p[25] += b * b;
            }
            #pragma unroll
            for (int q = 0; q < 26; q++) p[q] = wred(p[q]);
            __syncthreads();
            if (lane == 0) {
                #pragma unroll
                for (int q = 0; q < 26; q++) sfin[warp * 26 + q] = p[q];
            }
            __syncthreads();
            if (tid < 26) {
                float s = 0.f;
                for (int w = 0; w < NWARP; w++) s += sfin[w * 26 + tid];
                g_misc[tid] = s;
            }
            if (tid < 4)  g_misc[26 + tid] = b1[tid];
            if (tid < 16) g_misc[30 + tid] = wv_b[tid];
        }
        return;
    }

    // ===================== main launch (grid=148) =====================
    for (int idx = tid; idx < 8192; idx += TPB)
        ((float4*)sw)[idx] = ((const float4*)wv_w)[idx];
    for (int idx = tid; idx < 2048; idx += TPB)
        ((float4*)sw)[8192 + idx] = ((const float4*)w1)[idx];
    for (int idx = tid; idx < STAB_F; idx += TPB)
        stab[idx] = g_tab[idx];
    if (tid < SMISC_F) smisc[tid] = g_misc[tid];
    __syncthreads();

    int start = (int)(((long long)blockIdx.x * NTOK) / GRID);
    int end   = (int)(((long long)(blockIdx.x + 1) * NTOK) / GRID);

    float* part = spart + warp * 736;     // per-warp transpose scratch (720 used)
    float* sfw  = sfin + pair * 84;       // per-pair sums: [4 tok][21]
    const float* swr = sw + sub * 10 * 2048;  // this warp's 10 rows

    for (int t0 = start + pair * 4; t0 < end; t0 += NPAIR * 4) {
        const char* gp[4];
        #pragma unroll
        for (int i = 0; i < 4; i++) {
            int tt = t0 + i;
            if (tt > NTOK - 1) tt = NTOK - 1;
            gp[i] = (const char*)(hidden + (size_t)tt * 2048) + lane * 16;
        }

        float acc[10][4];
        #pragma unroll
        for (int r = 0; r < 10; r++)
            #pragma unroll
            for (int i = 0; i < 4; i++) acc[r][i] = 0.f;

        // 4-buffer rotation, lookahead 2 slices
        float4 b0[4], b1v[4], b2v[4], b3[4];
        #pragma unroll
        for (int i = 0; i < 4; i++) b0[i]  = *(const float4*)gp[i];
        #pragma unroll
        for (int i = 0; i < 4; i++) b1v[i] = *(const float4*)(gp[i] + 512);

        #pragma unroll 1
        for (int j = 0; j < 16; j += 4) {
            #pragma unroll
            for (int i = 0; i < 4; i++)
                b2v[i] = *(const float4*)(gp[i] + (j + 2) * 512);
            slice_fma(acc, b0, swr, j, lane);

            #pragma unroll
            for (int i = 0; i < 4; i++)
                b3[i] = *(const float4*)(gp[i] + (j + 3) * 512);
            slice_fma(acc, b1v, swr, j + 1, lane);

            {
                int jn = (j + 4 < 16) ? (j + 4) : 15;
                #pragma unroll
                for (int i = 0; i < 4; i++)
                    b0[i] = *(const float4*)(gp[i] + jn * 512);
            }
            slice_fma(acc, b2v, swr, j + 2, lane);

            {
                int jn = (j + 5 < 16) ? (j + 5) : 15;
                #pragma unroll
                for (int i = 0; i < 4; i++)
                    b1v[i] = *(const float4*)(gp[i] + jn * 512);
            }
            slice_fma(acc, b3, swr, j + 3, lane);
        }

        // --- chunked smem-transpose reduction: 2 chunks of 5 rows ---
        #pragma unroll
        for (int c = 0; c < 2; c++) {
            #pragma unroll
            for (int rl = 0; rl < 5; rl++) {
                #pragma unroll
                for (int i = 0; i < 4; i++)
                    part[(rl * 4 + i) * 36 + lane] = acc[c * 5 + rl][i];
            }
            __syncwarp();
            if (lane < 20) {
                const float4* p4 = (const float4*)(part + lane * 36);
                float4 q0 = p4[0], q1 = p4[1], q2 = p4[2], q3 = p4[3];
                float4 q4 = p4[4], q5 = p4[5], q6 = p4[6], q7 = p4[7];
                float s = ((q0.x + q0.y) + (q0.z + q0.w)) + ((q1.x + q1.y) + (q1.z + q1.w))
                        + ((q2.x + q2.y) + (q2.z + q2.w)) + ((q3.x + q3.y) + (q3.z + q3.w))
                        + ((q4.x + q4.y) + (q4.z + q4.w)) + ((q5.x + q5.y) + (q5.z + q5.w))
                        + ((q6.x + q6.y) + (q6.z + q6.w)) + ((q7.x + q7.y) + (q7.z + q7.w));
                sfw[(lane & 3) * 21 + sub * 10 + c * 5 + (lane >> 2)] = s;
            }
            __syncwarp();
        }

        pair_bar(pair);   // pair's 20 sums visible to both warps

        // --- epilogue: this warp handles tokens {sub*2, sub*2+1} ---
        int e  = lane >> 1;
        int fb = (lane & 1) << 3;
        const float* tb0 = stab + e * TSTRIDE + fb;

        #pragma unroll 1
        for (int i = sub * 2; i < sub * 2 + 2; i++) {
            if (t0 + i >= end) break;
            const float* sf = sfw + i * 21;
            float h0 = fmaxf(sf[16] + smisc[26], 0.f);
            float h1 = fmaxf(sf[17] + smisc[27], 0.f);
            float h2 = fmaxf(sf[18] + smisc[28], 0.f);
            float h3 = fmaxf(sf[19] + smisc[29], 0.f);
            float mu = (h0 * smisc[0] + h1 * smisc[1] + h2 * smisc[2] + h3 * smisc[3]
                        + smisc[24]) * (1.f / 2048.f);
            const float* Q = smisc + 4;
            float ex = smisc[25]
                     + 2.f * (h0 * smisc[20] + h1 * smisc[21] + h2 * smisc[22] + h3 * smisc[23])
                     + h0 * (h0 * Q[0]  + h1 * Q[1]  + h2 * Q[2]  + h3 * Q[3])
                     + h1 * (h0 * Q[4]  + h1 * Q[5]  + h2 * Q[6]  + h3 * Q[7])
                     + h2 * (h0 * Q[8]  + h1 * Q[9]  + h2 * Q[10] + h3 * Q[11])
                     + h3 * (h0 * Q[12] + h1 * Q[13] + h2 * Q[14] + h3 * Q[15]);
            ex *= (1.f / 2048.f);
            float rstd = rsqrtf(ex - mu * mu + 1e-5f);

            float Lv[8];
            float Lmax = -1e30f;
            #pragma unroll
            for (int ff = 0; ff < 8; ff++) {
                float a = tb0[4 * TSIZE + ff];                 // Tb
                a = fmaf(h0, tb0[0 * TSIZE + ff], a);
                a = fmaf(h1, tb0[1 * TSIZE + ff], a);
                a = fmaf(h2, tb0[2 * TSIZE + ff], a);
                a = fmaf(h3, tb0[3 * TSIZE + ff], a);
                a = fmaf(-mu, tb0[5 * TSIZE + ff], a);         // Gs
                float L = fmaf(rstd, a, tb0[6 * TSIZE + ff]);  // Bs
                Lv[ff] = L;
                Lmax = fmaxf(Lmax, L);
            }
            Lmax = fmaxf(Lmax, __shfl_xor_sync(~0u, Lmax, 1));
            float se = 0.f, gd = 0.f;
            #pragma unroll
            for (int ff = 0; ff < 8; ff++) {
                float p = __expf(Lv[ff] - Lmax);
                se += p;
                gd = fmaf(p, sf[fb + ff] + smisc[30 + fb + ff], gd);
            }
            se += __shfl_xor_sync(~0u, se, 1);
            gd += __shfl_xor_sync(~0u, gd, 1);
            float gate = gd / se;

            // rw = softmax over e (parity-preserving butterfly)
            float gmax = gate;
            #pragma unroll
            for (int m = 2; m <= 16; m <<= 1)
                gmax = fmaxf(gmax, __shfl_xor_sync(~0u, gmax, m));
            float er = __expf(gate - gmax);
            float es = er;
            #pragma unroll
            for (int m = 2; m <= 16; m <<= 1)
                es += __shfl_xor_sync(~0u, es, m);
            float rw = er / es;

            // top-2 over e with index tie-break (lower index wins)
            float v1 = rw, v2 = -1.f;
            int i1 = e, i2 = 16;
            #pragma unroll
            for (int m = 2; m <= 16; m <<= 1) {
                float ov1 = __shfl_xor_sync(~0u, v1, m);
                int   oi1 = __shfl_xor_sync(~0u, i1, m);
                float ov2 = __shfl_xor_sync(~0u, v2, m);
                int   oi2 = __shfl_xor_sync(~0u, i2, m);
                bool fw = (v1 > ov1) || (v1 == ov1 && i1 < oi1);
                float w1v = fw ? v1 : ov1;  int w1i = fw ? i1 : oi1;
                float l1v = fw ? ov1 : v1;  int l1i = fw ? oi1 : i1;
                float c2v = fw ? v2 : ov2;  int c2i = fw ? i2 : oi2;
                bool sv = (l1v > c2v) || (l1v == c2v && l1i < c2i);
                v1 = w1v; i1 = w1i;
                v2 = sv ? l1v : c2v;
                i2 = sv ? l1i : c2i;
            }

            float texp = __expf((v2 - v1) * 10.f);
            float inv = 1.f / (1.f + texp);
            float ov = (e == i1) ? inv : ((e == i2) ? texp * inv : 0.f);
            if (!(lane & 1)) out[(size_t)(t0 + i) * 16 + e] = ov;
        }

        pair_bar(pair);   // sums consumed; safe to overwrite next iteration
    }
}

// ---------------------------------------------------------------------------
extern "C" void kernel_launch(void* const* d_in, const int* in_sizes, int n_in,
                              void* d_out, int out_size)
{
    const float* hidden = (const float*)d_in[0];
    const float* ee     = (const float*)d_in[1];
    const float* gamma  = (const float*)d_in[2];
    const float* beta   = (const float*)d_in[3];
    const float* wv_w   = (const float*)d_in[4];
    const float* wv_b   = (const float*)d_in[5];
    const float* w1     = (const float*)d_in[6];
    const float* b1     = (const float*)d_in[7];
    const float* w2     = (const float*)d_in[8];
    const float* b2     = (const float*)d_in[9];
    const float* wq     = (const float*)d_in[10];
    const float* wk     = (const float*)d_in[11];
    float* out = (float*)d_out;

    cudaFuncSetAttribute(fused_kernel, cudaFuncAttributeMaxDynamicSharedMemorySize,
                         SMEM_BYTES);

    fused_kernel<<<PREP_GRID, TPB, SMEM_BYTES>>>(hidden, ee, gamma, beta, wv_w, wv_b,
                                                 w1, b1, w2, b2, wq, wk, out, 0);
    fused_kernel<<<GRID, TPB, SMEM_BYTES>>>(hidden, ee, gamma, beta, wv_w, wv_b,
                                            w1, b1, w2, b2, wq, wk, out, 1);
}

// round 13
// speedup vs baseline: 1.1418x; 1.1418x over previous
#include <cuda_runtime.h>
#include <cstdint>
#include <math.h>

// ---------------------------------------------------------------------------
// Hybrid router. B*S=16384 tokens, IN=2048, E=16, D=128, A=128, R=4, top_k=2.
// TWO launches of the SAME kernel (same smem config):
//   mode=0, grid=148: main. Blocks 0..15 first run prep (block f computes
//       k[f]/Mk[f]/tables[:,f]; block 0 adds rank-4 moments -> globals) and get
//       a smaller token share. All blocks then stream tokens: pure GEMM
//       (20 rows x 2048 dots, plain fp32 FMA, j-unroll-2 LDG prefetch),
//       writing per-token row-sums to g_sums. NO barriers, NO epilogue.
//   mode=1, grid=148: epilogue. Reads g_sums/g_tab/g_misc, does softmaxes +
//       top-2 sharpened softmax, writes out. 2 tokens per warp per pass.
// ---------------------------------------------------------------------------

#define NTOK 16384
#define GRID 148
#define TPB  512
#define NWARP 16
#define NPAIR 8

#define TSTRIDE 35
#define TSIZE   544

// smem layout (floats)
#define SW_F      40960            // 20 rows x 2048 weights (16 Wv + 4 w1)
#define STAB_F    (7 * TSIZE)      // 3808
#define SMISC_F   64
#define SFIN_F    672              // scratch (prep reductions)
#define SPART_F   (NWARP * 736)    // per-warp reduce scratch (also prep scratch)
#define OFF_STAB  SW_F
#define OFF_SMISC (OFF_STAB + STAB_F)
#define OFF_SFIN  (OFF_SMISC + SMISC_F)
#define OFF_SPART (OFF_SFIN + SFIN_F)
#define SMEM_FLOATS (OFF_SPART + SPART_F)
#define SMEM_BYTES  (SMEM_FLOATS * 4)

// token split: prep blocks (0..15) get fewer tokens
#define PREP_TOK   96
#define REST_BASE  (16 * PREP_TOK)            // 1536
#define REST_TOK   (NTOK - REST_BASE)         // 14848 over 132 blocks

__device__ float g_tab[7 * TSIZE];
__device__ float g_misc[SMISC_F];
__device__ float g_sums[NTOK * 21];

// ---------------------------------------------------------------------------
__device__ __forceinline__ float wred(float v) {
    #pragma unroll
    for (int m = 16; m; m >>= 1) v += __shfl_xor_sync(~0u, v, m);
    return v;
}

// ---------------------------------------------------------------------------
__global__ void __launch_bounds__(TPB, 1)
fused_kernel(const float* __restrict__ hidden, const float* __restrict__ ee,
             const float* __restrict__ gamma, const float* __restrict__ beta,
             const float* __restrict__ wv_w, const float* __restrict__ wv_b,
             const float* __restrict__ w1, const float* __restrict__ b1,
             const float* __restrict__ w2, const float* __restrict__ b2,
             const float* __restrict__ wq, const float* __restrict__ wk,
             float* __restrict__ out, int mode)
{
    extern __shared__ float smem[];
    float* sw    = smem;
    float* stab  = smem + OFF_STAB;
    float* smisc = smem + OFF_SMISC;
    float* sfin  = smem + OFF_SFIN;
    float* spart = smem + OFF_SPART;

    int tid = threadIdx.x, lane = tid & 31, warp = tid >> 5;
    int pair = warp >> 1, sub = warp & 1;

    if (mode == 1) {
        // ===================== epilogue launch =====================
        for (int idx = tid; idx < STAB_F; idx += TPB)
            stab[idx] = g_tab[idx];
        if (tid < SMISC_F) smisc[tid] = g_misc[tid];
        __syncthreads();

        int e  = lane >> 1;
        int fb = (lane & 1) << 3;
        const float* tb0 = stab + e * TSTRIDE + fb;
        int gw = blockIdx.x * NWARP + warp;

        for (int t0 = gw * 2; t0 < NTOK; t0 += GRID * NWARP * 2) {
            #pragma unroll 1
            for (int i = 0; i < 2; i++) {
                int t = t0 + i;
                if (t >= NTOK) break;
                const float* sf = g_sums + t * 21;
                float h0 = fmaxf(sf[16] + smisc[26], 0.f);
                float h1 = fmaxf(sf[17] + smisc[27], 0.f);
                float h2 = fmaxf(sf[18] + smisc[28], 0.f);
                float h3 = fmaxf(sf[19] + smisc[29], 0.f);
                float mu = (h0 * smisc[0] + h1 * smisc[1] + h2 * smisc[2]
                            + h3 * smisc[3] + smisc[24]) * (1.f / 2048.f);
                const float* Q = smisc + 4;
                float ex = smisc[25]
                         + 2.f * (h0 * smisc[20] + h1 * smisc[21]
                                + h2 * smisc[22] + h3 * smisc[23])
                         + h0 * (h0 * Q[0]  + h1 * Q[1]  + h2 * Q[2]  + h3 * Q[3])
                         + h1 * (h0 * Q[4]  + h1 * Q[5]  + h2 * Q[6]  + h3 * Q[7])
                         + h2 * (h0 * Q[8]  + h1 * Q[9]  + h2 * Q[10] + h3 * Q[11])
                         + h3 * (h0 * Q[12] + h1 * Q[13] + h2 * Q[14] + h3 * Q[15]);
                ex *= (1.f / 2048.f);
                float rstd = rsqrtf(ex - mu * mu + 1e-5f);

                float Lv[8];
                float Lmax = -1e30f;
                #pragma unroll
                for (int ff = 0; ff < 8; ff++) {
                    float a = tb0[4 * TSIZE + ff];                 // Tb
                    a = fmaf(h0, tb0[0 * TSIZE + ff], a);
                    a = fmaf(h1, tb0[1 * TSIZE + ff], a);
                    a = fmaf(h2, tb0[2 * TSIZE + ff], a);
                    a = fmaf(h3, tb0[3 * TSIZE + ff], a);
                    a = fmaf(-mu, tb0[5 * TSIZE + ff], a);         // Gs
                    float L = fmaf(rstd, a, tb0[6 * TSIZE + ff]);  // Bs
                    Lv[ff] = L;
                    Lmax = fmaxf(Lmax, L);
                }
                Lmax = fmaxf(Lmax, __shfl_xor_sync(~0u, Lmax, 1));
                float se = 0.f, gd = 0.f;
                #pragma unroll
                for (int ff = 0; ff < 8; ff++) {
                    float p = __expf(Lv[ff] - Lmax);
                    se += p;
                    gd = fmaf(p, sf[fb + ff] + smisc[30 + fb + ff], gd);
                }
                se += __shfl_xor_sync(~0u, se, 1);
                gd += __shfl_xor_sync(~0u, gd, 1);
                float gate = gd / se;

                // rw = softmax over e (parity-preserving butterfly)
                float gmax = gate;
                #pragma unroll
                for (int m = 2; m <= 16; m <<= 1)
                    gmax = fmaxf(gmax, __shfl_xor_sync(~0u, gmax, m));
                float er = __expf(gate - gmax);
                float es = er;
                #pragma unroll
                for (int m = 2; m <= 16; m <<= 1)
                    es += __shfl_xor_sync(~0u, es, m);
                float rw = er / es;

                // top-2 over e with index tie-break (lower index wins)
                float v1 = rw, v2 = -1.f;
                int i1 = e, i2 = 16;
                #pragma unroll
                for (int m = 2; m <= 16; m <<= 1) {
                    float ov1 = __shfl_xor_sync(~0u, v1, m);
                    int   oi1 = __shfl_xor_sync(~0u, i1, m);
                    float ov2 = __shfl_xor_sync(~0u, v2, m);
                    int   oi2 = __shfl_xor_sync(~0u, i2, m);
                    bool fw = (v1 > ov1) || (v1 == ov1 && i1 < oi1);
                    float w1v = fw ? v1 : ov1;  int w1i = fw ? i1 : oi1;
                    float l1v = fw ? ov1 : v1;  int l1i = fw ? oi1 : i1;
                    float c2v = fw ? v2 : ov2;  int c2i = fw ? i2 : oi2;
                    bool sv = (l1v > c2v) || (l1v == c2v && l1i < c2i);
                    v1 = w1v; i1 = w1i;
                    v2 = sv ? l1v : c2v;
                    i2 = sv ? l1i : c2i;
                }

                float texp = __expf((v2 - v1) * 10.f);
                float inv = 1.f / (1.f + texp);
                float ov = (e == i1) ? inv : ((e == i2) ? texp * inv : 0.f);
                if (!(lane & 1)) out[(size_t)t * 16 + e] = ov;
            }
        }
        return;
    }

    // ===================== main launch (grid=148) =====================
    // stage 0: weights -> smem (all blocks)
    for (int idx = tid; idx < 8192; idx += TPB)
        ((float4*)sw)[idx] = ((const float4*)wv_w)[idx];
    for (int idx = tid; idx < 2048; idx += TPB)
        ((float4*)sw)[8192 + idx] = ((const float4*)w1)[idx];

    // stage 1: blocks 0..15 run prep (block f handles table column f)
    if (blockIdx.x < 16) {
        int f = blockIdx.x;
        float* sge  = spart;           // 2048: LN(ee), later reused for final Mk
        float* skv  = spart + 2048;    // 128:  k[f][:]
        float* smkp = spart + 4096;    // NWARP*128: Mk partials
        float* sred = sfin;            // scratch

        // --- LN of expert_embedding over all 2048 ---
        {
            float ls = 0.f, lq = 0.f;
            for (int i = tid; i < 2048; i += TPB) {
                float v = ee[i];
                sge[i] = v; ls += v; lq += v * v;
            }
            ls = wred(ls); lq = wred(lq);
            if (lane == 0) { sred[warp] = ls; sred[16 + warp] = lq; }
            __syncthreads();
            if (tid == 0) {
                float s = 0.f, q = 0.f;
                for (int i = 0; i < NWARP; i++) { s += sred[i]; q += sred[16 + i]; }
                float mu = s * (1.0f / 2048.0f);
                float var = q * (1.0f / 2048.0f) - mu * mu;
                sred[32] = mu; sred[33] = rsqrtf(var + 1e-5f);
            }
            __syncthreads();
            float mu = sred[32], rs = sred[33];
            for (int i = tid; i < 2048; i += TPB)
                sge[i] = (sge[i] - mu) * rs * gamma[i] + beta[i];
            __syncthreads();
        }

        // --- k[f][a]: warp w computes a in [8w, 8w+8) ---
        {
            float4 g4 = ((const float4*)(sge + f * 128))[lane];
            float p[8];
            #pragma unroll
            for (int q = 0; q < 8; q++) {
                float4 w4 = ((const float4*)(wk + (warp * 8 + q) * 128))[lane];
                p[q] = fmaf(g4.x, w4.x, fmaf(g4.y, w4.y,
                       fmaf(g4.z, w4.z, g4.w * w4.w)));
            }
            #pragma unroll
            for (int m = 16; m; m >>= 1) {
                #pragma unroll
                for (int q = 0; q < 8; q++)
                    p[q] += __shfl_xor_sync(~0u, p[q], m);
            }
            if (lane == 0) {
                #pragma unroll
                for (int q = 0; q < 8; q++) skv[warp * 8 + q] = p[q];
            }
        }
        __syncthreads();

        // --- Mk[f][d] partials: warp w covers a in [8w, 8w+8), lanes cover d ---
        {
            const float4* wq4 = (const float4*)wq + lane;
            float4 a4 = make_float4(0.f, 0.f, 0.f, 0.f);
            #pragma unroll
            for (int aa = 0; aa < 8; aa++) {
                int a = warp * 8 + aa;
                float s = skv[a];
                float4 w4 = wq4[a * 32];
                a4.x = fmaf(s, w4.x, a4.x);
                a4.y = fmaf(s, w4.y, a4.y);
                a4.z = fmaf(s, w4.z, a4.z);
                a4.w = fmaf(s, w4.w, a4.w);
            }
            ((float4*)(smkp + warp * 128))[lane] = a4;
        }
        __syncthreads();
        if (tid < 128) {
            float s = 0.f;
            #pragma unroll
            for (int w = 0; w < NWARP; w++) s += smkp[w * 128 + tid];
            sge[tid] = s * 0.08838834764831845f;  // 1/sqrt(128)
        }
        __syncthreads();

        // --- tables T0..T3, Tb, Gs, Bs for (e=warp, f) ---
        {
            int e = warp;
            int o = e * 128 + lane * 4;
            float4 mk = ((const float4*)sge)[lane];
            float4 ga = *(const float4*)(gamma + o);
            float4 be = *(const float4*)(beta + o);
            float4 bb = *(const float4*)(b2 + o);
            float4 wA = *(const float4*)(w2 + (o + 0) * 4);
            float4 wB = *(const float4*)(w2 + (o + 1) * 4);
            float4 wC = *(const float4*)(w2 + (o + 2) * 4);
            float4 wD = *(const float4*)(w2 + (o + 3) * 4);
            float m0 = mk.x * ga.x, m1 = mk.y * ga.y, m2 = mk.z * ga.z, m3 = mk.w * ga.w;
            float t0 = m0 * wA.x + m1 * wB.x + m2 * wC.x + m3 * wD.x;
            float t1 = m0 * wA.y + m1 * wB.y + m2 * wC.y + m3 * wD.y;
            float t2 = m0 * wA.z + m1 * wB.z + m2 * wC.z + m3 * wD.z;
            float t3 = m0 * wA.w + m1 * wB.w + m2 * wC.w + m3 * wD.w;
            float tb = m0 * bb.x + m1 * bb.y + m2 * bb.z + m3 * bb.w;
            float gs = m0 + m1 + m2 + m3;
            float bs = mk.x * be.x + mk.y * be.y + mk.z * be.z + mk.w * be.w;
            #pragma unroll
            for (int m = 16; m; m >>= 1) {
                t0 += __shfl_xor_sync(~0u, t0, m);
                t1 += __shfl_xor_sync(~0u, t1, m);
                t2 += __shfl_xor_sync(~0u, t2, m);
                t3 += __shfl_xor_sync(~0u, t3, m);
                tb += __shfl_xor_sync(~0u, tb, m);
                gs += __shfl_xor_sync(~0u, gs, m);
                bs += __shfl_xor_sync(~0u, bs, m);
            }
            if (lane == 0) {
                int oo = e * TSTRIDE + f;
                g_tab[0 * TSIZE + oo] = t0;
                g_tab[1 * TSIZE + oo] = t1;
                g_tab[2 * TSIZE + oo] = t2;
                g_tab[3 * TSIZE + oo] = t3;
                g_tab[4 * TSIZE + oo] = tb;
                g_tab[5 * TSIZE + oo] = gs;
                g_tab[6 * TSIZE + oo] = bs;
            }
        }

        // --- rank-4 moments (block 0 only) ---
        if (blockIdx.x == 0) {
            float p[26];
            #pragma unroll
            for (int q = 0; q < 26; q++) p[q] = 0.f;
            for (int o = tid; o < 2048; o += TPB) {
                float4 w4 = *(const float4*)(w2 + o * 4);
                float b = b2[o];
                float w0v = w4.x, w1v = w4.y, w2v = w4.z, w3v = w4.w;
                p[0] += w0v; p[1] += w1v; p[2] += w2v; p[3] += w3v;
                p[4]  += w0v * w0v; p[5]  += w0v * w1v; p[6]  += w0v * w2v; p[7]  += w0v * w3v;
                p[8]  += w1v * w0v; p[9]  += w1v * w1v; p[10] += w1v * w2v; p[11] += w1v * w3v;
                p[12] += w2v * w0v; p[13] += w2v * w1v; p[14] += w2v * w2v; p[15] += w2v * w3v;
                p[16] += w3v * w0v; p[17] += w3v * w1v; p[18] += w3v * w2v; p[19] += w3v * w3v;
                p[20] += w0v * b; p[21] += w1v * b; p[22] += w2v * b; p[23] += w3v * b;
                p[24] += b; p[25] += b * b;
            }
            #pragma unroll
            for (int q = 0; q < 26; q++) p[q] = wred(p[q]);
            __syncthreads();
            if (lane == 0) {
                #pragma unroll
                for (int q = 0; q < 26; q++) sfin[warp * 26 + q] = p[q];
            }
            __syncthreads();
            if (tid < 26) {
                float s = 0.f;
                for (int w = 0; w < NWARP; w++) s += sfin[w * 26 + tid];
                g_misc[tid] = s;
            }
            if (tid < 4)  g_misc[26 + tid] = b1[tid];
            if (tid < 16) g_misc[30 + tid] = wv_b[tid];
        }
        __syncthreads();   // spart free for token loop
    }
    __syncthreads();

    // stage 2: token stream (pure GEMM -> g_sums; no barriers, no epilogue)
    int start, end;
    if (blockIdx.x < 16) {
        start = blockIdx.x * PREP_TOK;
        end   = start + PREP_TOK;
    } else {
        int idx = blockIdx.x - 16;
        start = REST_BASE + (int)(((long long)idx * REST_TOK) / 132);
        end   = REST_BASE + (int)(((long long)(idx + 1) * REST_TOK) / 132);
    }

    float* part = spart + warp * 736;        // per-warp transpose scratch
    const float* swr = sw + sub * 10 * 2048; // this warp's 10 rows

    for (int t0 = start + pair * 4; t0 < end; t0 += NPAIR * 4) {
        const char* gp[4];
        #pragma unroll
        for (int i = 0; i < 4; i++) {
            int tt = t0 + i;
            if (tt > NTOK - 1) tt = NTOK - 1;
            gp[i] = (const char*)(hidden + (size_t)tt * 2048) + lane * 16;
        }

        float acc[10][4];
        #pragma unroll
        for (int r = 0; r < 10; r++)
            #pragma unroll
            for (int i = 0; i < 4; i++) acc[r][i] = 0.f;

        float4 ha[4], hb[4];
        #pragma unroll
        for (int i = 0; i < 4; i++) ha[i] = *(const float4*)gp[i];

        #pragma unroll 1
        for (int j = 0; j < 16; j += 2) {
            #pragma unroll
            for (int i = 0; i < 4; i++)
                hb[i] = *(const float4*)(gp[i] + (j + 1) * 512);
            const float4* wj0 = (const float4*)(swr + j * 128) + lane;
            #pragma unroll
            for (int r = 0; r < 10; r++) {
                float4 wv = wj0[r * 512];
                #pragma unroll
                for (int i = 0; i < 4; i++) {
                    acc[r][i] = fmaf(ha[i].x, wv.x, acc[r][i]);
                    acc[r][i] = fmaf(ha[i].y, wv.y, acc[r][i]);
                    acc[r][i] = fmaf(ha[i].z, wv.z, acc[r][i]);
                    acc[r][i] = fmaf(ha[i].w, wv.w, acc[r][i]);
                }
            }
            if (j < 14) {
                #pragma unroll
                for (int i = 0; i < 4; i++)
                    ha[i] = *(const float4*)(gp[i] + (j + 2) * 512);
            }
            const float4* wj1 = (const float4*)(swr + (j + 1) * 128) + lane;
            #pragma unroll
            for (int r = 0; r < 10; r++) {
                float4 wv = wj1[r * 512];
                #pragma unroll
                for (int i = 0; i < 4; i++) {
                    acc[r][i] = fmaf(hb[i].x, wv.x, acc[r][i]);
                    acc[r][i] = fmaf(hb[i].y, wv.y, acc[r][i]);
                    acc[r][i] = fmaf(hb[i].z, wv.z, acc[r][i]);
                    acc[r][i] = fmaf(hb[i].w, wv.w, acc[r][i]);
                }
            }
        }

        // --- chunked smem-transpose reduction -> g_sums (2 chunks of 5 rows) ---
        #pragma unroll
        for (int c = 0; c < 2; c++) {
            #pragma unroll
            for (int rl = 0; rl < 5; rl++) {
                #pragma unroll
                for (int i = 0; i < 4; i++)
                    part[(rl * 4 + i) * 36 + lane] = acc[c * 5 + rl][i];
            }
            __syncwarp();
            if (lane < 20) {
                const float4* p4 = (const float4*)(part + lane * 36);
                float4 q0 = p4[0], q1 = p4[1], q2 = p4[2], q3 = p4[3];
                float4 q4 = p4[4], q5 = p4[5], q6 = p4[6], q7 = p4[7];
                float s = ((q0.x + q0.y) + (q0.z + q0.w)) + ((q1.x + q1.y) + (q1.z + q1.w))
                        + ((q2.x + q2.y) + (q2.z + q2.w)) + ((q3.x + q3.y) + (q3.z + q3.w))
                        + ((q4.x + q4.y) + (q4.z + q4.w)) + ((q5.x + q5.y) + (q5.z + q5.w))
                        + ((q6.x + q6.y) + (q6.z + q6.w)) + ((q7.x + q7.y) + (q7.z + q7.w));
                int tt = t0 + (lane & 3);
                if (tt < end)
                    g_sums[tt * 21 + sub * 10 + c * 5 + (lane >> 2)] = s;
            }
            __syncwarp();
        }
    }
}

// ---------------------------------------------------------------------------
extern "C" void kernel_launch(void* const* d_in, const int* in_sizes, int n_in,
                              void* d_out, int out_size)
{
    const float* hidden = (const float*)d_in[0];
    const float* ee     = (const float*)d_in[1];
    const float* gamma  = (const float*)d_in[2];
    const float* beta   = (const float*)d_in[3];
    const float* wv_w   = (const float*)d_in[4];
    const float* wv_b   = (const float*)d_in[5];
    const float* w1     = (const float*)d_in[6];
    const float* b1     = (const float*)d_in[7];
    const float* w2     = (const float*)d_in[8];
    const float* b2     = (const float*)d_in[9];
    const float* wq     = (const float*)d_in[10];
    const float* wk     = (const float*)d_in[11];
    float* out = (float*)d_out;

    cudaFuncSetAttribute(fused_kernel, cudaFuncAttributeMaxDynamicSharedMemorySize,
                         SMEM_BYTES);

    fused_kernel<<<GRID, TPB, SMEM_BYTES>>>(hidden, ee, gamma, beta, wv_w, wv_b,
                                            w1, b1, w2, b2, wq, wk, out, 0);
    fused_kernel<<<GRID, TPB, SMEM_BYTES>>>(hidden, ee, gamma, beta, wv_w, wv_b,
                                            w1, b1, w2, b2, wq, wk, out, 1);
}

// round 16
// speedup vs baseline: 1.2174x; 1.0662x over previous
#include <cuda_runtime.h>
#include <cstdint>
#include <math.h>

// ---------------------------------------------------------------------------
// Hybrid router. B*S=16384 tokens, IN=2048, E=16, D=128, A=128, R=4, top_k=2.
// TWO launches of the SAME kernel (same smem config):
//   mode=0, grid=148: main. Blocks 0..15 first run prep (block f computes
//       k[f]/Mk[f]/tables[:,f]; block 0 adds rank-4 moments -> globals) and get
//       a smaller token share. All blocks then stream tokens: pure GEMM
//       (20 rows x 2048 dots, plain fp32 FMA, j-unroll-2 LDG prefetch),
//       writing per-token row-sums to g_sums TRANSPOSED [r][t].
//   mode=1, grid=148: epilogue, ONE TOKEN PER THREAD (no shuffles): 512
//       working warps spread across all SMs; tables read via float4 broadcast
//       LDS; coalesced g_sums reads; scalar softmaxes + top-2 in registers.
// ---------------------------------------------------------------------------

#define NTOK 16384
#define GRID 148
#define TPB  512
#define NWARP 16
#define NPAIR 8

#define TSTRIDE 36
#define TSIZE   576

// smem layout (floats)
#define SW_F      40960            // 20 rows x 2048 weights (16 Wv + 4 w1)
#define STAB_F    (7 * TSIZE)      // 4032
#define SMISC_F   64
#define SFIN_F    672              // scratch (prep reductions)
#define SPART_F   (NWARP * 736)    // per-warp reduce scratch (also prep scratch)
#define OFF_STAB  SW_F
#define OFF_SMISC (OFF_STAB + STAB_F)
#define OFF_SFIN  (OFF_SMISC + SMISC_F)
#define OFF_SPART (OFF_SFIN + SFIN_F)
#define SMEM_FLOATS (OFF_SPART + SPART_F)
#define SMEM_BYTES  (SMEM_FLOATS * 4)

// token split: prep blocks (0..15) get fewer tokens
#define PREP_TOK   96
#define REST_BASE  (16 * PREP_TOK)            // 1536
#define REST_TOK   (NTOK - REST_BASE)         // 14848 over 132 blocks

__device__ float g_tab[7 * TSIZE];
__device__ float g_misc[SMISC_F];
__device__ float g_sums[21 * NTOK];           // transposed: [row][token]

// ---------------------------------------------------------------------------
__device__ __forceinline__ float wred(float v) {
    #pragma unroll
    for (int m = 16; m; m >>= 1) v += __shfl_xor_sync(~0u, v, m);
    return v;
}

// ---------------------------------------------------------------------------
__global__ void __launch_bounds__(TPB, 1)
fused_kernel(const float* __restrict__ hidden, const float* __restrict__ ee,
             const float* __restrict__ gamma, const float* __restrict__ beta,
             const float* __restrict__ wv_w, const float* __restrict__ wv_b,
             const float* __restrict__ w1, const float* __restrict__ b1,
             const float* __restrict__ w2, const float* __restrict__ b2,
             const float* __restrict__ wq, const float* __restrict__ wk,
             float* __restrict__ out, int mode)
{
    extern __shared__ float smem[];
    float* sw    = smem;
    float* stab  = smem + OFF_STAB;
    float* smisc = smem + OFF_SMISC;
    float* sfin  = smem + OFF_SFIN;
    float* spart = smem + OFF_SPART;

    int tid = threadIdx.x, lane = tid & 31, warp = tid >> 5;
    int pair = warp >> 1, sub = warp & 1;

    if (mode == 1) {
        // ============== epilogue: one token per thread ==============
        for (int idx = tid; idx < STAB_F; idx += TPB)
            stab[idx] = g_tab[idx];
        if (tid < SMISC_F) smisc[tid] = g_misc[tid];
        __syncthreads();

        int gw = blockIdx.x + GRID * warp;     // spread working warps over SMs
        int t  = gw * 32 + lane;
        if (t >= NTOK) return;

        // coalesced reads of this token's 20 row-sums
        float wv[16];
        #pragma unroll
        for (int r = 0; r < 16; r++)
            wv[r] = g_sums[r * NTOK + t] + smisc[30 + r];
        float h0 = fmaxf(g_sums[16 * NTOK + t] + smisc[26], 0.f);
        float h1 = fmaxf(g_sums[17 * NTOK + t] + smisc[27], 0.f);
        float h2 = fmaxf(g_sums[18 * NTOK + t] + smisc[28], 0.f);
        float h3 = fmaxf(g_sums[19 * NTOK + t] + smisc[29], 0.f);

        float mu = (h0 * smisc[0] + h1 * smisc[1] + h2 * smisc[2]
                    + h3 * smisc[3] + smisc[24]) * (1.f / 2048.f);
        const float* Q = smisc + 4;
        float ex = smisc[25]
                 + 2.f * (h0 * smisc[20] + h1 * smisc[21]
                        + h2 * smisc[22] + h3 * smisc[23])
                 + h0 * (h0 * Q[0]  + h1 * Q[1]  + h2 * Q[2]  + h3 * Q[3])
                 + h1 * (h0 * Q[4]  + h1 * Q[5]  + h2 * Q[6]  + h3 * Q[7])
                 + h2 * (h0 * Q[8]  + h1 * Q[9]  + h2 * Q[10] + h3 * Q[11])
                 + h3 * (h0 * Q[12] + h1 * Q[13] + h2 * Q[14] + h3 * Q[15]);
        ex *= (1.f / 2048.f);
        float rstd = rsqrtf(ex - mu * mu + 1e-5f);

        // routing gates: for each e, softmax over f folded with input gate
        float gate[16];
        #pragma unroll
        for (int e = 0; e < 16; e++) {
            const float* tb = stab + e * TSTRIDE;
            float L[16], Lmax = -1e30f;
            #pragma unroll
            for (int fq = 0; fq < 4; fq++) {
                float4 T0 = *(const float4*)(tb + 0 * TSIZE + fq * 4);
                float4 T1 = *(const float4*)(tb + 1 * TSIZE + fq * 4);
                float4 T2 = *(const float4*)(tb + 2 * TSIZE + fq * 4);
                float4 T3 = *(const float4*)(tb + 3 * TSIZE + fq * 4);
                float4 TB = *(const float4*)(tb + 4 * TSIZE + fq * 4);
                float4 GS = *(const float4*)(tb + 5 * TSIZE + fq * 4);
                float4 BS = *(const float4*)(tb + 6 * TSIZE + fq * 4);
                float a;
                a = TB.x; a = fmaf(h0, T0.x, a); a = fmaf(h1, T1.x, a);
                a = fmaf(h2, T2.x, a); a = fmaf(h3, T3.x, a); a = fmaf(-mu, GS.x, a);
                L[fq * 4 + 0] = fmaf(rstd, a, BS.x);
                a = TB.y; a = fmaf(h0, T0.y, a); a = fmaf(h1, T1.y, a);
                a = fmaf(h2, T2.y, a); a = fmaf(h3, T3.y, a); a = fmaf(-mu, GS.y, a);
                L[fq * 4 + 1] = fmaf(rstd, a, BS.y);
                a = TB.z; a = fmaf(h0, T0.z, a); a = fmaf(h1, T1.z, a);
                a = fmaf(h2, T2.z, a); a = fmaf(h3, T3.z, a); a = fmaf(-mu, GS.z, a);
                L[fq * 4 + 2] = fmaf(rstd, a, BS.z);
                a = TB.w; a = fmaf(h0, T0.w, a); a = fmaf(h1, T1.w, a);
                a = fmaf(h2, T2.w, a); a = fmaf(h3, T3.w, a); a = fmaf(-mu, GS.w, a);
                L[fq * 4 + 3] = fmaf(rstd, a, BS.w);
            }
            #pragma unroll
            for (int f = 0; f < 16; f++) Lmax = fmaxf(Lmax, L[f]);
            float se = 0.f, gd = 0.f;
            #pragma unroll
            for (int f = 0; f < 16; f++) {
                float p = __expf(L[f] - Lmax);
                se += p;
                gd = fmaf(p, wv[f], gd);
            }
            gate[e] = gd / se;
        }

        // softmax over e
        float gmax = -1e30f;
        #pragma unroll
        for (int e = 0; e < 16; e++) gmax = fmaxf(gmax, gate[e]);
        float er[16], es = 0.f;
        #pragma unroll
        for (int e = 0; e < 16; e++) { er[e] = __expf(gate[e] - gmax); es += er[e]; }

        // top-2 (lower index wins ties)
        float v1 = -1.f, v2 = -1.f;
        int i1 = -1, i2 = -1;
        #pragma unroll
        for (int e = 0; e < 16; e++) {
            float v = er[e];
            bool gt1 = v > v1;
            bool gt2 = v > v2;
            // shift current best to second if displaced
            v2 = gt1 ? v1 : (gt2 ? v : v2);
            i2 = gt1 ? i1 : (gt2 ? e : i2);
            v1 = gt1 ? v : v1;
            i1 = gt1 ? e : i1;
        }

        // sharpened softmax over {rw1, rw2} at temperature 0.1
        float texp = __expf((v2 - v1) * (10.f / es));
        float inv  = 1.f / (1.f + texp);
        float sec  = texp * inv;

        float4* op = (float4*)(out + (size_t)t * 16);
        #pragma unroll
        for (int q = 0; q < 4; q++) {
            float4 o;
            int e0 = q * 4;
            o.x = (e0 + 0 == i1) ? inv : ((e0 + 0 == i2) ? sec : 0.f);
            o.y = (e0 + 1 == i1) ? inv : ((e0 + 1 == i2) ? sec : 0.f);
            o.z = (e0 + 2 == i1) ? inv : ((e0 + 2 == i2) ? sec : 0.f);
            o.w = (e0 + 3 == i1) ? inv : ((e0 + 3 == i2) ? sec : 0.f);
            op[q] = o;
        }
        return;
    }

    // ===================== main launch (grid=148) =====================
    // stage 0: weights -> smem (all blocks)
    for (int idx = tid; idx < 8192; idx += TPB)
        ((float4*)sw)[idx] = ((const float4*)wv_w)[idx];
    for (int idx = tid; idx < 2048; idx += TPB)
        ((float4*)sw)[8192 + idx] = ((const float4*)w1)[idx];

    // stage 1: blocks 0..15 run prep (block f handles table column f)
    if (blockIdx.x < 16) {
        int f = blockIdx.x;
        float* sge  = spart;           // 2048: LN(ee), later reused for final Mk
        float* skv  = spart + 2048;    // 128:  k[f][:]
        float* smkp = spart + 4096;    // NWARP*128: Mk partials
        float* sred = sfin;            // scratch

        // --- LN of expert_embedding over all 2048 ---
        {
            float ls = 0.f, lq = 0.f;
            for (int i = tid; i < 2048; i += TPB) {
                float v = ee[i];
                sge[i] = v; ls += v; lq += v * v;
            }
            ls = wred(ls); lq = wred(lq);
            if (lane == 0) { sred[warp] = ls; sred[16 + warp] = lq; }
            __syncthreads();
            if (tid == 0) {
                float s = 0.f, q = 0.f;
                for (int i = 0; i < NWARP; i++) { s += sred[i]; q += sred[16 + i]; }
                float mu = s * (1.0f / 2048.0f);
                float var = q * (1.0f / 2048.0f) - mu * mu;
                sred[32] = mu; sred[33] = rsqrtf(var + 1e-5f);
            }
            __syncthreads();
            float mu = sred[32], rs = sred[33];
            for (int i = tid; i < 2048; i += TPB)
                sge[i] = (sge[i] - mu) * rs * gamma[i] + beta[i];
            __syncthreads();
        }

        // --- k[f][a]: warp w computes a in [8w, 8w+8) ---
        {
            float4 g4 = ((const float4*)(sge + f * 128))[lane];
            float p[8];
            #pragma unroll
            for (int q = 0; q < 8; q++) {
                float4 w4 = ((const float4*)(wk + (warp * 8 + q) * 128))[lane];
                p[q] = fmaf(g4.x, w4.x, fmaf(g4.y, w4.y,
                       fmaf(g4.z, w4.z, g4.w * w4.w)));
            }
            #pragma unroll
            for (int m = 16; m; m >>= 1) {
                #pragma unroll
                for (int q = 0; q < 8; q++)
                    p[q] += __shfl_xor_sync(~0u, p[q], m);
            }
            if (lane == 0) {
                #pragma unroll
                for (int q = 0; q < 8; q++) skv[warp * 8 + q] = p[q];
            }
        }
        __syncthreads();

        // --- Mk[f][d] partials: warp w covers a in [8w, 8w+8), lanes cover d ---
        {
            const float4* wq4 = (const float4*)wq + lane;
            float4 a4 = make_float4(0.f, 0.f, 0.f, 0.f);
            #pragma unroll
            for (int aa = 0; aa < 8; aa++) {
                int a = warp * 8 + aa;
                float s = skv[a];
                float4 w4 = wq4[a * 32];
                a4.x = fmaf(s, w4.x, a4.x);
                a4.y = fmaf(s, w4.y, a4.y);
                a4.z = fmaf(s, w4.z, a4.z);
                a4.w = fmaf(s, w4.w, a4.w);
            }
            ((float4*)(smkp + warp * 128))[lane] = a4;
        }
        __syncthreads();
        if (tid < 128) {
            float s = 0.f;
            #pragma unroll
            for (int w = 0; w < NWARP; w++) s += smkp[w * 128 + tid];
            sge[tid] = s * 0.08838834764831845f;  // 1/sqrt(128)
        }
        __syncthreads();

        // --- tables T0..T3, Tb, Gs, Bs for (e=warp, f) ---
        {
            int e = warp;
            int o = e * 128 + lane * 4;
            float4 mk = ((const float4*)sge)[lane];
            float4 ga = *(const float4*)(gamma + o);
            float4 be = *(const float4*)(beta + o);
            float4 bb = *(const float4*)(b2 + o);
            float4 wA = *(const float4*)(w2 + (o + 0) * 4);
            float4 wB = *(const float4*)(w2 + (o + 1) * 4);
            float4 wC = *(const float4*)(w2 + (o + 2) * 4);
            float4 wD = *(const float4*)(w2 + (o + 3) * 4);
            float m0 = mk.x * ga.x, m1 = mk.y * ga.y, m2 = mk.z * ga.z, m3 = mk.w * ga.w;
            float t0 = m0 * wA.x + m1 * wB.x + m2 * wC.x + m3 * wD.x;
            float t1 = m0 * wA.y + m1 * wB.y + m2 * wC.y + m3 * wD.y;
            float t2 = m0 * wA.z + m1 * wB.z + m2 * wC.z + m3 * wD.z;
            float t3 = m0 * wA.w + m1 * wB.w + m2 * wC.w + m3 * wD.w;
            float tb = m0 * bb.x + m1 * bb.y + m2 * bb.z + m3 * bb.w;
            float gs = m0 + m1 + m2 + m3;
            float bs = mk.x * be.x + mk.y * be.y + mk.z * be.z + mk.w * be.w;
            #pragma unroll
            for (int m = 16; m; m >>= 1) {
                t0 += __shfl_xor_sync(~0u, t0, m);
                t1 += __shfl_xor_sync(~0u, t1, m);
                t2 += __shfl_xor_sync(~0u, t2, m);
                t3 += __shfl_xor_sync(~0u, t3, m);
                tb += __shfl_xor_sync(~0u, tb, m);
                gs += __shfl_xor_sync(~0u, gs, m);
                bs += __shfl_xor_sync(~0u, bs, m);
            }
            if (lane == 0) {
                int oo = e * TSTRIDE + f;
                g_tab[0 * TSIZE + oo] = t0;
                g_tab[1 * TSIZE + oo] = t1;
                g_tab[2 * TSIZE + oo] = t2;
                g_tab[3 * TSIZE + oo] = t3;
                g_tab[4 * TSIZE + oo] = tb;
                g_tab[5 * TSIZE + oo] = gs;
                g_tab[6 * TSIZE + oo] = bs;
            }
        }

        // --- rank-4 moments (block 0 only) ---
        if (blockIdx.x == 0) {
            float p[26];
            #pragma unroll
            for (int q = 0; q < 26; q++) p[q] = 0.f;
            for (int o = tid; o < 2048; o += TPB) {
                float4 w4 = *(const float4*)(w2 + o * 4);
                float b = b2[o];
                float w0v = w4.x, w1v = w4.y, w2v = w4.z, w3v = w4.w;
                p[0] += w0v; p[1] += w1v; p[2] += w2v; p[3] += w3v;
                p[4]  += w0v * w0v; p[5]  += w0v * w1v; p[6]  += w0v * w2v; p[7]  += w0v * w3v;
                p[8]  += w1v * w0v; p[9]  += w1v * w1v; p[10] += w1v * w2v; p[11] += w1v * w3v;
                p[12] += w2v * w0v; p[13] += w2v * w1v; p[14] += w2v * w2v; p[15] += w2v * w3v;
                p[16] += w3v * w0v; p[17] += w3v * w1v; p[18] += w3v * w2v; p[19] += w3v * w3v;
                p[20] += w0v * b; p[21] += w1v * b; p[22] += w2v * b; p[23] += w3v * b;
                p[24] += b; p[25] += b * b;
            }
            #pragma unroll
            for (int q = 0; q < 26; q++) p[q] = wred(p[q]);
            __syncthreads();
            if (lane == 0) {
                #pragma unroll
                for (int q = 0; q < 26; q++) sfin[warp * 26 + q] = p[q];
            }
            __syncthreads();
            if (tid < 26) {
                float s = 0.f;
                for (int w = 0; w < NWARP; w++) s += sfin[w * 26 + tid];
                g_misc[tid] = s;
            }
            if (tid < 4)  g_misc[26 + tid] = b1[tid];
            if (tid < 16) g_misc[30 + tid] = wv_b[tid];
        }
        __syncthreads();   // spart free for token loop
    }
    __syncthreads();

    // stage 2: token stream (pure GEMM -> g_sums transposed; no barriers)
    int start, end;
    if (blockIdx.x < 16) {
        start = blockIdx.x * PREP_TOK;
        end   = start + PREP_TOK;
    } else {
        int idx = blockIdx.x - 16;
        start = REST_BASE + (int)(((long long)idx * REST_TOK) / 132);
        end   = REST_BASE + (int)(((long long)(idx + 1) * REST_TOK) / 132);
    }

    float* part = spart + warp * 736;        // per-warp transpose scratch
    const float* swr = sw + sub * 10 * 2048; // this warp's 10 rows

    for (int t0 = start + pair * 4; t0 < end; t0 += NPAIR * 4) {
        const char* gp[4];
        #pragma unroll
        for (int i = 0; i < 4; i++) {
            int tt = t0 + i;
            if (tt > NTOK - 1) tt = NTOK - 1;
            gp[i] = (const char*)(hidden + (size_t)tt * 2048) + lane * 16;
        }

        float acc[10][4];
        #pragma unroll
        for (int r = 0; r < 10; r++)
            #pragma unroll
            for (int i = 0; i < 4; i++) acc[r][i] = 0.f;

        float4 ha[4], hb[4];
        #pragma unroll
        for (int i = 0; i < 4; i++) ha[i] = *(const float4*)gp[i];

        #pragma unroll 1
        for (int j = 0; j < 16; j += 2) {
            #pragma unroll
            for (int i = 0; i < 4; i++)
                hb[i] = *(const float4*)(gp[i] + (j + 1) * 512);
            const float4* wj0 = (const float4*)(swr + j * 128) + lane;
            #pragma unroll
            for (int r = 0; r < 10; r++) {
                float4 wv = wj0[r * 512];
                #pragma unroll
                for (int i = 0; i < 4; i++) {
                    acc[r][i] = fmaf(ha[i].x, wv.x, acc[r][i]);
                    acc[r][i] = fmaf(ha[i].y, wv.y, acc[r][i]);
                    acc[r][i] = fmaf(ha[i].z, wv.z, acc[r][i]);
                    acc[r][i] = fmaf(ha[i].w, wv.w, acc[r][i]);
                }
            }
            if (j < 14) {
                #pragma unroll
                for (int i = 0; i < 4; i++)
                    ha[i] = *(const float4*)(gp[i] + (j + 2) * 512);
            }
            const float4* wj1 = (const float4*)(swr + (j + 1) * 128) + lane;
            #pragma unroll
            for (int r = 0; r < 10; r++) {
                float4 wv = wj1[r * 512];
                #pragma unroll
                for (int i = 0; i < 4; i++) {
                    acc[r][i] = fmaf(hb[i].x, wv.x, acc[r][i]);
                    acc[r][i] = fmaf(hb[i].y, wv.y, acc[r][i]);
                    acc[r][i] = fmaf(hb[i].z, wv.z, acc[r][i]);
                    acc[r][i] = fmaf(hb[i].w, wv.w, acc[r][i]);
                }
            }
        }

        // --- chunked smem-transpose reduction -> g_sums[r][t] ---
        #pragma unroll
        for (int c = 0; c < 2; c++) {
            #pragma unroll
            for (int rl = 0; rl < 5; rl++) {
                #pragma unroll
                for (int i = 0; i < 4; i++)
                    part[(rl * 4 + i) * 36 + lane] = acc[c * 5 + rl][i];
            }
            __syncwarp();
            if (lane < 20) {
                const float4* p4 = (const float4*)(part + lane * 36);
                float4 q0 = p4[0], q1 = p4[1], q2 = p4[2], q3 = p4[3];
                float4 q4 = p4[4], q5 = p4[5], q6 = p4[6], q7 = p4[7];
                float s = ((q0.x + q0.y) + (q0.z + q0.w)) + ((q1.x + q1.y) + (q1.z + q1.w))
                        + ((q2.x + q2.y) + (q2.z + q2.w)) + ((q3.x + q3.y) + (q3.z + q3.w))
                        + ((q4.x + q4.y) + (q4.z + q4.w)) + ((q5.x + q5.y) + (q5.z + q5.w))
                        + ((q6.x + q6.y) + (q6.z + q6.w)) + ((q7.x + q7.y) + (q7.z + q7.w));
                int tt = t0 + (lane & 3);
                int rr = sub * 10 + c * 5 + (lane >> 2);
                if (tt < end)
                    g_sums[rr * NTOK + tt] = s;
            }
            __syncwarp();
        }
    }
}

// ---------------------------------------------------------------------------
extern "C" void kernel_launch(void* const* d_in, const int* in_sizes, int n_in,
                              void* d_out, int out_size)
{
    const float* hidden = (const float*)d_in[0];
    const float* ee     = (const float*)d_in[1];
    const float* gamma  = (const float*)d_in[2];
    const float* beta   = (const float*)d_in[3];
    const float* wv_w   = (const float*)d_in[4];
    const float* wv_b   = (const float*)d_in[5];
    const float* w1     = (const float*)d_in[6];
    const float* b1     = (const float*)d_in[7];
    const float* w2     = (const float*)d_in[8];
    const float* b2     = (const float*)d_in[9];
    const float* wq     = (const float*)d_in[10];
    const float* wk     = (const float*)d_in[11];
    float* out = (float*)d_out;

    cudaFuncSetAttribute(fused_kernel, cudaFuncAttributeMaxDynamicSharedMemorySize,
                         SMEM_BYTES);

    fused_kernel<<<GRID, TPB, SMEM_BYTES>>>(hidden, ee, gamma, beta, wv_w, wv_b,
                                            w1, b1, w2, b2, wq, wk, out, 0);
    fused_kernel<<<GRID, TPB, SMEM_BYTES>>>(hidden, ee, gamma, beta, wv_w, wv_b,
                                            w1, b1, w2, b2, wq, wk, out, 1);
}